// round 10
// baseline (speedup 1.0000x reference)
#include <cuda_runtime.h>
#include <cuda_bf16.h>
#include <cstdint>
#include <cstddef>

// Problem dims: x [4,2048,4096] -> M=8192, K=4096; w [16384,4096] -> N=16384
#define MDIM 8192
#define KDIM 4096
#define NDIM 16384
#define MAXV 448.0f
#define EPSV 1e-12f

#define XAB 1024
#define WAB 2048

// ---------------- device scratch ----------------
__device__ float g_part[XAB + WAB];
__device__ float g_scales[3];                       // sx, sw, 1/(sx*sw)
__device__ uint8_t g_xq[(size_t)MDIM * KDIM];       // 32 MB e4m3 (scaled domain)
__device__ uint8_t g_wq[(size_t)NDIM * KDIM];       // 64 MB e4m3 (scaled domain)

// ---------------- launch 1: fused amax partials ----------------
__global__ void amax_fused_kernel(const float4* __restrict__ x, const float4* __restrict__ w) {
    __shared__ float sred[8];
    int seg = (blockIdx.x < XAB) ? 0 : 1;
    const float4* p = seg ? w : x;
    size_t n4 = seg ? ((size_t)NDIM * KDIM / 4) : ((size_t)MDIM * KDIM / 4);
    int b = seg ? (blockIdx.x - XAB) : blockIdx.x;
    size_t nb = seg ? WAB : XAB;

    float m = 0.f;
    size_t stride = nb * blockDim.x;
    for (size_t i = (size_t)b * blockDim.x + threadIdx.x; i < n4; i += stride) {
        float4 v = p[i];
        m = fmaxf(m, fminf(fabsf(v.x), MAXV));
        m = fmaxf(m, fminf(fabsf(v.y), MAXV));
        m = fmaxf(m, fminf(fabsf(v.z), MAXV));
        m = fmaxf(m, fminf(fabsf(v.w), MAXV));
    }
#pragma unroll
    for (int o = 16; o > 0; o >>= 1) m = fmaxf(m, __shfl_xor_sync(0xffffffffu, m, o));
    if ((threadIdx.x & 31) == 0) sred[threadIdx.x >> 5] = m;
    __syncthreads();
    if (threadIdx.x == 0) {
        float r = sred[0];
#pragma unroll
        for (int i = 1; i < 8; ++i) r = fmaxf(r, sred[i]);
        g_part[blockIdx.x] = r;
    }
}

// ---------------- launch 2: reduce partials -> scales ----------------
__global__ void scales_kernel() {
    __shared__ float sx_s[32], sw_s[32];
    int t = threadIdx.x, lane = t & 31, wrp = t >> 5;
    float mx = 0.f, mw = 0.f;
    for (int i = t; i < XAB; i += 1024) mx = fmaxf(mx, g_part[i]);
    for (int i = t; i < WAB; i += 1024) mw = fmaxf(mw, g_part[XAB + i]);
#pragma unroll
    for (int o = 16; o > 0; o >>= 1) {
        mx = fmaxf(mx, __shfl_xor_sync(0xffffffffu, mx, o));
        mw = fmaxf(mw, __shfl_xor_sync(0xffffffffu, mw, o));
    }
    if (lane == 0) { sx_s[wrp] = mx; sw_s[wrp] = mw; }
    __syncthreads();
    if (t == 0) {
        float ax = EPSV, aw = EPSV;
#pragma unroll
        for (int i = 0; i < 32; ++i) { ax = fmaxf(ax, sx_s[i]); aw = fmaxf(aw, sw_s[i]); }
        float sx = MAXV / ax, sw = MAXV / aw;
        g_scales[0] = sx;
        g_scales[1] = sw;
        g_scales[2] = (1.f / sx) * (1.f / sw);
    }
}

// ---------------- fake-quantize in scaled domain, pack to e4m3 ----------------
__device__ __forceinline__ float fqs(float v, float scale) {
    float c = fminf(fmaxf(v, -MAXV), MAXV);
    float s = c * scale;
    float mag = fmaxf(fabsf(s), EPSV);
    int e;
    frexpf(mag, &e);
    float r = rintf(ldexpf(mag, 4 - e));
    float q = ldexpf(r, e - 4);
    return copysignf(q, s);
}

__device__ __forceinline__ uint32_t pack4_e4m3(float a, float b, float c, float d) {
    uint16_t lo, hi;
    asm("cvt.rn.satfinite.e4m3x2.f32 %0, %2, %1;" : "=h"(lo) : "f"(a), "f"(b));
    asm("cvt.rn.satfinite.e4m3x2.f32 %0, %2, %1;" : "=h"(hi) : "f"(c), "f"(d));
    return (uint32_t)lo | ((uint32_t)hi << 16);
}

// ---------------- launch 3: fused quantize ----------------
__global__ void quant_fused_kernel(const float4* __restrict__ x, const float4* __restrict__ w) {
    int seg = (blockIdx.x < 2048) ? 0 : 1;
    const float4* in = seg ? w : x;
    uint32_t* outq = (uint32_t*)(seg ? g_wq : g_xq);
    size_t n4 = seg ? ((size_t)NDIM * KDIM / 4) : ((size_t)MDIM * KDIM / 4);
    int b = seg ? (blockIdx.x - 2048) : blockIdx.x;
    size_t nb = seg ? 4096 : 2048;
    float s = g_scales[seg];
    size_t stride = nb * blockDim.x;
    for (size_t i = (size_t)b * blockDim.x + threadIdx.x; i < n4; i += stride) {
        float4 v = in[i];
        outq[i] = pack4_e4m3(fqs(v.x, s), fqs(v.y, s), fqs(v.z, s), fqs(v.w, s));
    }
}

// =======================================================================
// launch 4: FP8 mma.sync GEMM, CTA 128x128, warp tile 64x64, BK=128,
// 3-stage cp.async ring. One barrier per 4 k32 sub-steps. Only ONE
// fragment set live at any time (R7/R9 lesson: two sets -> spills).
// =======================================================================
#define BM 128
#define BN 128
#define BK 128
#define STAGES 3
#define NKIT (KDIM / BK)            // 32
#define PITCHB 144                  // 128B data + 16B pad: conflict-free ldmatrix
#define TILE_B (128 * PITCHB)       // 18432 per operand
#define STAGE_B (2 * TILE_B)        // 36864
#define SMEM_TOT (STAGES * STAGE_B) // 110592 (2 CTAs/SM: 221184 <= 228KB)

__device__ __forceinline__ uint32_t smem_u32(const void* p) {
    return (uint32_t)__cvta_generic_to_shared(p);
}
__device__ __forceinline__ void cp16s(uint32_t dst, const void* src) {
    asm volatile("cp.async.cg.shared.global [%0], [%1], 16;\n" :: "r"(dst), "l"(src));
}
__device__ __forceinline__ void ldsm_x4(uint32_t* r, uint32_t addr) {
    asm volatile("ldmatrix.sync.aligned.m8n8.x4.shared.b16 {%0,%1,%2,%3}, [%4];\n"
                 : "=r"(r[0]), "=r"(r[1]), "=r"(r[2]), "=r"(r[3]) : "r"(addr));
}
__device__ __forceinline__ void mma_fp8(float* c, const uint32_t* a, const uint32_t* b) {
    asm volatile("mma.sync.aligned.m16n8k32.row.col.f32.e4m3.e4m3.f32 "
                 "{%0,%1,%2,%3}, {%4,%5,%6,%7}, {%8,%9}, {%0,%1,%2,%3};\n"
                 : "+f"(c[0]), "+f"(c[1]), "+f"(c[2]), "+f"(c[3])
                 : "r"(a[0]), "r"(a[1]), "r"(a[2]), "r"(a[3]), "r"(b[0]), "r"(b[1]));
}

__device__ __forceinline__ void load_stage(uint8_t* smem, int s,
                                           const uint8_t* __restrict__ gA,
                                           const uint8_t* __restrict__ gB,
                                           int k0, int tid) {
    uint32_t stA = smem_u32(smem + (size_t)s * STAGE_B);
    uint32_t stB = stA + TILE_B;
#pragma unroll
    for (int j = 0; j < 16; ++j) {
        int chunk = j * 128 + tid;          // 0..2047; first 1024 = A, rest = B
        if (j < 8) {
            int r = chunk >> 3, c = (chunk & 7) * 16;
            cp16s(stA + r * PITCHB + c, gA + (size_t)r * KDIM + k0 + c);
        } else {
            int bc = chunk - 1024;
            int r = bc >> 3, c = (bc & 7) * 16;
            cp16s(stB + r * PITCHB + c, gB + (size_t)r * KDIM + k0 + c);
        }
    }
    asm volatile("cp.async.commit_group;\n" ::: "memory");
}

// per-warp fragment load for one k32 sub-step (ks = 0..3)
__device__ __forceinline__ void load_frags(uint32_t stA, uint32_t stB, int wm, int wn,
                                           int lane, int ks,
                                           uint32_t a[4][4], uint32_t b[8][2]) {
#pragma unroll
    for (int i = 0; i < 4; ++i) {
        uint32_t addr = stA + (wm + i * 16 + (lane & 15)) * PITCHB
                            + ks * 32 + (lane >> 4) * 16;
        ldsm_x4(a[i], addr);
    }
#pragma unroll
    for (int jj = 0; jj < 4; ++jj) {
        int g = lane >> 3;
        int row = wn + jj * 16 + ((g >> 1) << 3) + (lane & 7);
        int col = ks * 32 + ((g & 1) << 4);
        uint32_t r[4];
        ldsm_x4(r, stB + row * PITCHB + col);
        b[2 * jj][0] = r[0]; b[2 * jj][1] = r[1];
        b[2 * jj + 1][0] = r[2]; b[2 * jj + 1][1] = r[3];
    }
}

__global__ void __launch_bounds__(128, 2)
gemm_fp8_kernel(const float* __restrict__ bias, float* __restrict__ out) {
    extern __shared__ uint8_t smem[];

    int tid = threadIdx.x;
    int lane = tid & 31, warp = tid >> 5;
    int wm = (warp >> 1) * 64;
    int wn = (warp & 1) * 64;
    int mblk = blockIdx.x, nblk = blockIdx.y;

    const uint8_t* gA = g_xq + (size_t)mblk * BM * KDIM;
    const uint8_t* gB = g_wq + (size_t)nblk * BN * KDIM;

    float acc[4][8][4];
#pragma unroll
    for (int i = 0; i < 4; ++i)
#pragma unroll
        for (int j = 0; j < 8; ++j)
#pragma unroll
            for (int k = 0; k < 4; ++k) acc[i][j][k] = 0.f;

    // prologue: fill 2 of 3 stages
    load_stage(smem, 0, gA, gB, 0, tid);
    load_stage(smem, 1, gA, gB, BK, tid);

    // stage 0 complete + visible for iter 0's pre-barrier ldsm
    asm volatile("cp.async.wait_group 1;\n" ::: "memory");
    __syncthreads();

    int sidx = 0;                        // stage slot for current kt (mod 3)
    for (int kt = 0; kt < NKIT; ++kt) {
        uint32_t stA = smem_u32(smem + (size_t)sidx * STAGE_B);
        uint32_t stB = stA + TILE_B;

        // ks0 fragments before the barrier: stage kt complete (wait at prev
        // iter) and visible (prev barrier). Hides under barrier wait.
        uint32_t a[4][4], b[8][2];
        load_frags(stA, stB, wm, wn, lane, 0, a, b);

        // stage kt+1 (issued a full iteration ago) must be complete before
        // this barrier so next iter's pre-barrier ldsm is legal
        asm volatile("cp.async.wait_group 0;\n" ::: "memory");
        __syncthreads();

        // refill slot of stage kt-1 (reads finished, protected by barrier)
        if (kt + 2 < NKIT) {
            int ns = sidx + 2; if (ns >= STAGES) ns -= STAGES;
            load_stage(smem, ns, gA, gB, (kt + 2) * BK, tid);
        }

        // 4 k32 sub-steps; one fragment set live at a time (reg reuse)
#pragma unroll
        for (int i = 0; i < 4; ++i)
#pragma unroll
            for (int j = 0; j < 8; ++j)
                mma_fp8(acc[i][j], a[i], b[j]);
#pragma unroll
        for (int ks = 1; ks < 4; ++ks) {
            load_frags(stA, stB, wm, wn, lane, ks, a, b);
#pragma unroll
            for (int i = 0; i < 4; ++i)
#pragma unroll
                for (int j = 0; j < 8; ++j)
                    mma_fp8(acc[i][j], a[i], b[j]);
        }

        if (++sidx == STAGES) sidx = 0;
    }

    float inv = g_scales[2];
    int m0 = mblk * BM + wm;
    int n0 = nblk * BN + wn;
#pragma unroll
    for (int i = 0; i < 4; ++i) {
        int m = m0 + i * 16 + (lane >> 2);
#pragma unroll
        for (int j = 0; j < 8; ++j) {
            int n = n0 + j * 8 + ((lane & 3) << 1);
            float b0 = bias[n], b1 = bias[n + 1];
            float2 v0 = make_float2(acc[i][j][0] * inv + b0, acc[i][j][1] * inv + b1);
            float2 v1 = make_float2(acc[i][j][2] * inv + b0, acc[i][j][3] * inv + b1);
            *reinterpret_cast<float2*>(&out[(size_t)m * NDIM + n]) = v0;
            *reinterpret_cast<float2*>(&out[(size_t)(m + 8) * NDIM + n]) = v1;
        }
    }
}

// ---------------- 4 launches; GEMM is launch #4 (profiled slot) ----------------
extern "C" void kernel_launch(void* const* d_in, const int* in_sizes, int n_in,
                              void* d_out, int out_size) {
    const float* x    = (const float*)d_in[0];
    const float* w    = (const float*)d_in[1];
    const float* bias = (const float*)d_in[2];
    float* out = (float*)d_out;

    amax_fused_kernel<<<XAB + WAB, 256>>>((const float4*)x, (const float4*)w);
    scales_kernel<<<1, 1024>>>();
    quant_fused_kernel<<<2048 + 4096, 256>>>((const float4*)x, (const float4*)w);

    static bool attr_done = false;
    if (!attr_done) {
        cudaFuncSetAttribute(gemm_fp8_kernel,
                             cudaFuncAttributeMaxDynamicSharedMemorySize, SMEM_TOT);
        attr_done = true;
    }
    dim3 grid(MDIM / BM, NDIM / BN);   // (64, 128): M fastest; A panel L2-resident
    gemm_fp8_kernel<<<grid, 128, SMEM_TOT>>>(bias, out);
}

// round 11
// speedup vs baseline: 1.4470x; 1.4470x over previous
#include <cuda_runtime.h>
#include <cuda_bf16.h>
#include <cstdint>
#include <cstddef>

// Problem dims: x [4,2048,4096] -> M=8192, K=4096; w [16384,4096] -> N=16384
#define MDIM 8192
#define KDIM 4096
#define NDIM 16384
#define MAXV 448.0f
#define EPSV 1e-12f

#define XAB 1024
#define WAB 2048

// ---------------- device scratch ----------------
__device__ float g_part[XAB + WAB];
__device__ float g_scales[3];                       // sx, sw, 1/(sx*sw)
__device__ uint8_t g_xq[(size_t)MDIM * KDIM];       // 32 MB e4m3 (scaled domain)
__device__ uint8_t g_wq[(size_t)NDIM * KDIM];       // 64 MB e4m3 (scaled domain)

// ---------------- launch 1: fused amax partials (4 indep accumulators) ----------------
__global__ void amax_fused_kernel(const float4* __restrict__ x, const float4* __restrict__ w) {
    __shared__ float sred[8];
    int seg = (blockIdx.x < XAB) ? 0 : 1;
    const float4* p = seg ? w : x;
    size_t n4 = seg ? ((size_t)NDIM * KDIM / 4) : ((size_t)MDIM * KDIM / 4);
    int b = seg ? (blockIdx.x - XAB) : blockIdx.x;
    size_t nb = seg ? WAB : XAB;

    float m0 = 0.f, m1 = 0.f, m2 = 0.f, m3 = 0.f;
    size_t stride = nb * blockDim.x;
    for (size_t i = (size_t)b * blockDim.x + threadIdx.x; i < n4; i += stride) {
        float4 v = p[i];
        m0 = fmaxf(m0, fabsf(v.x));
        m1 = fmaxf(m1, fabsf(v.y));
        m2 = fmaxf(m2, fabsf(v.z));
        m3 = fmaxf(m3, fabsf(v.w));
    }
    float m = fminf(fmaxf(fmaxf(m0, m1), fmaxf(m2, m3)), MAXV);
#pragma unroll
    for (int o = 16; o > 0; o >>= 1) m = fmaxf(m, __shfl_xor_sync(0xffffffffu, m, o));
    if ((threadIdx.x & 31) == 0) sred[threadIdx.x >> 5] = m;
    __syncthreads();
    if (threadIdx.x == 0) {
        float r = sred[0];
#pragma unroll
        for (int i = 1; i < 8; ++i) r = fmaxf(r, sred[i]);
        g_part[blockIdx.x] = r;
    }
}

// ---------------- launch 2: reduce partials -> scales ----------------
__global__ void scales_kernel() {
    __shared__ float sx_s[32], sw_s[32];
    int t = threadIdx.x, lane = t & 31, wrp = t >> 5;
    float mx = 0.f, mw = 0.f;
    for (int i = t; i < XAB; i += 1024) mx = fmaxf(mx, g_part[i]);
    for (int i = t; i < WAB; i += 1024) mw = fmaxf(mw, g_part[XAB + i]);
#pragma unroll
    for (int o = 16; o > 0; o >>= 1) {
        mx = fmaxf(mx, __shfl_xor_sync(0xffffffffu, mx, o));
        mw = fmaxf(mw, __shfl_xor_sync(0xffffffffu, mw, o));
    }
    if (lane == 0) { sx_s[wrp] = mx; sw_s[wrp] = mw; }
    __syncthreads();
    if (t == 0) {
        float ax = EPSV, aw = EPSV;
#pragma unroll
        for (int i = 0; i < 32; ++i) { ax = fmaxf(ax, sx_s[i]); aw = fmaxf(aw, sw_s[i]); }
        float sx = MAXV / ax, sw = MAXV / aw;
        g_scales[0] = sx;
        g_scales[1] = sw;
        g_scales[2] = (1.f / sx) * (1.f / sw);
    }
}

// ---------------- fake-quantize in scaled domain, pack to e4m3 ----------------
__device__ __forceinline__ float fqs(float v, float scale) {
    float c = fminf(fmaxf(v, -MAXV), MAXV);
    float s = c * scale;
    float mag = fmaxf(fabsf(s), EPSV);
    int e;
    frexpf(mag, &e);
    float r = rintf(ldexpf(mag, 4 - e));
    float q = ldexpf(r, e - 4);
    return copysignf(q, s);
}

__device__ __forceinline__ uint32_t pack4_e4m3(float a, float b, float c, float d) {
    uint16_t lo, hi;
    asm("cvt.rn.satfinite.e4m3x2.f32 %0, %2, %1;" : "=h"(lo) : "f"(a), "f"(b));
    asm("cvt.rn.satfinite.e4m3x2.f32 %0, %2, %1;" : "=h"(hi) : "f"(c), "f"(d));
    return (uint32_t)lo | ((uint32_t)hi << 16);
}

// ---------------- launch 3: fused quantize ----------------
__global__ void quant_fused_kernel(const float4* __restrict__ x, const float4* __restrict__ w) {
    int seg = (blockIdx.x < 2048) ? 0 : 1;
    const float4* in = seg ? w : x;
    uint32_t* outq = (uint32_t*)(seg ? g_wq : g_xq);
    size_t n4 = seg ? ((size_t)NDIM * KDIM / 4) : ((size_t)MDIM * KDIM / 4);
    int b = seg ? (blockIdx.x - 2048) : blockIdx.x;
    size_t nb = seg ? 4096 : 2048;
    float s = g_scales[seg];
    size_t stride = nb * blockDim.x;
    for (size_t i = (size_t)b * blockDim.x + threadIdx.x; i < n4; i += stride) {
        float4 v = in[i];
        outq[i] = pack4_e4m3(fqs(v.x, s), fqs(v.y, s), fqs(v.z, s), fqs(v.w, s));
    }
}

// =======================================================================
// launch 4: FP8 mma.sync GEMM, CTA 128x128, warp tile 64x64, BK=64.
// Warp-private double-buffered staging: each warp cp.asyncs its OWN
// A/B panels; mainloop has ZERO __syncthreads (per-warp wait_group only).
// =======================================================================
#define BM 128
#define BN 128
#define BK 64
#define NKIT (KDIM / BK)            // 64
#define PITCHB 80                   // 64B data + 16B pad per row
#define PANEL_B (64 * PITCHB)       // 5120: one 64-row panel
#define WARP_B (2 * PANEL_B)        // 10240: A panel + B panel per warp
#define STAGE_B (4 * WARP_B)        // 40960 per stage (4 warps)
#define SMEM_TOT (2 * STAGE_B)      // 81920 (2 CTAs/SM -> 160KB)

__device__ __forceinline__ uint32_t smem_u32(const void* p) {
    return (uint32_t)__cvta_generic_to_shared(p);
}
__device__ __forceinline__ void cp16s(uint32_t dst, const void* src) {
    asm volatile("cp.async.cg.shared.global [%0], [%1], 16;\n" :: "r"(dst), "l"(src));
}
__device__ __forceinline__ void ldsm_x4(uint32_t* r, uint32_t addr) {
    asm volatile("ldmatrix.sync.aligned.m8n8.x4.shared.b16 {%0,%1,%2,%3}, [%4];\n"
                 : "=r"(r[0]), "=r"(r[1]), "=r"(r[2]), "=r"(r[3]) : "r"(addr));
}
__device__ __forceinline__ void mma_fp8(float* c, const uint32_t* a, const uint32_t* b) {
    asm volatile("mma.sync.aligned.m16n8k32.row.col.f32.e4m3.e4m3.f32 "
                 "{%0,%1,%2,%3}, {%4,%5,%6,%7}, {%8,%9}, {%0,%1,%2,%3};\n"
                 : "+f"(c[0]), "+f"(c[1]), "+f"(c[2]), "+f"(c[3])
                 : "r"(a[0]), "r"(a[1]), "r"(a[2]), "r"(a[3]), "r"(b[0]), "r"(b[1]));
}

// one warp loads its own 64-row A panel + 64-row B panel for one stage
__device__ __forceinline__ void load_stage_w(uint32_t base,
                                             const uint8_t* __restrict__ gA,
                                             const uint8_t* __restrict__ gB,
                                             int k0, int lane) {
#pragma unroll
    for (int j = 0; j < 8; ++j) {
        int chunk = j * 32 + lane;            // 0..255
        int r = chunk >> 2, c = (chunk & 3) * 16;
        cp16s(base + r * PITCHB + c, gA + (size_t)r * KDIM + k0 + c);
    }
#pragma unroll
    for (int j = 0; j < 8; ++j) {
        int chunk = j * 32 + lane;
        int r = chunk >> 2, c = (chunk & 3) * 16;
        cp16s(base + PANEL_B + r * PITCHB + c, gB + (size_t)r * KDIM + k0 + c);
    }
    asm volatile("cp.async.commit_group;\n" ::: "memory");
}

// fragment load for one k32 sub-step from this warp's private panels
__device__ __forceinline__ void load_frags(uint32_t pA, uint32_t pB,
                                           int lane, int ks,
                                           uint32_t a[4][4], uint32_t b[8][2]) {
#pragma unroll
    for (int i = 0; i < 4; ++i) {
        uint32_t addr = pA + (i * 16 + (lane & 15)) * PITCHB
                           + ks * 32 + (lane >> 4) * 16;
        ldsm_x4(a[i], addr);
    }
#pragma unroll
    for (int jj = 0; jj < 4; ++jj) {
        int g = lane >> 3;
        int row = jj * 16 + ((g >> 1) << 3) + (lane & 7);
        int col = ks * 32 + ((g & 1) << 4);
        uint32_t r[4];
        ldsm_x4(r, pB + row * PITCHB + col);
        b[2 * jj][0] = r[0]; b[2 * jj][1] = r[1];
        b[2 * jj + 1][0] = r[2]; b[2 * jj + 1][1] = r[3];
    }
}

__global__ void __launch_bounds__(128, 2)
gemm_fp8_kernel(const float* __restrict__ bias, float* __restrict__ out) {
    extern __shared__ uint8_t smem[];

    int tid = threadIdx.x;
    int lane = tid & 31, warp = tid >> 5;
    int wm = (warp >> 1) * 64;
    int wn = (warp & 1) * 64;
    int mblk = blockIdx.x, nblk = blockIdx.y;

    // this warp's global panels
    const uint8_t* gA = g_xq + (size_t)(mblk * BM + wm) * KDIM;
    const uint8_t* gB = g_wq + (size_t)(nblk * BN + wn) * KDIM;

    // this warp's private smem regions (double buffer)
    uint32_t sb = smem_u32(smem);
    uint32_t wbase0 = sb + warp * WARP_B;
    uint32_t wbase1 = sb + STAGE_B + warp * WARP_B;

    float acc[4][8][4];
#pragma unroll
    for (int i = 0; i < 4; ++i)
#pragma unroll
        for (int j = 0; j < 8; ++j)
#pragma unroll
            for (int k = 0; k < 4; ++k) acc[i][j][k] = 0.f;

    load_stage_w(wbase0, gA, gB, 0, lane);

    for (int kt = 0; kt < NKIT; ++kt) {
        uint32_t cur = (kt & 1) ? wbase1 : wbase0;
        uint32_t nxt = (kt & 1) ? wbase0 : wbase1;

        if (kt + 1 < NKIT) {
            // prefetch next stage into the other buffer (its previous
            // occupant was consumed in the previous iteration)
            load_stage_w(nxt, gA, gB, (kt + 1) * BK, lane);
            asm volatile("cp.async.wait_group 1;\n" ::: "memory");  // stage kt done
        } else {
            asm volatile("cp.async.wait_group 0;\n" ::: "memory");
        }

        uint32_t pA = cur, pB = cur + PANEL_B;
        uint32_t a[4][4], b[8][2];
        load_frags(pA, pB, lane, 0, a, b);
#pragma unroll
        for (int i = 0; i < 4; ++i)
#pragma unroll
            for (int j = 0; j < 8; ++j)
                mma_fp8(acc[i][j], a[i], b[j]);
        load_frags(pA, pB, lane, 1, a, b);
#pragma unroll
        for (int i = 0; i < 4; ++i)
#pragma unroll
            for (int j = 0; j < 8; ++j)
                mma_fp8(acc[i][j], a[i], b[j]);
    }

    float inv = g_scales[2];
    int m0 = mblk * BM + wm;
    int n0 = nblk * BN + wn;
#pragma unroll
    for (int i = 0; i < 4; ++i) {
        int m = m0 + i * 16 + (lane >> 2);
#pragma unroll
        for (int j = 0; j < 8; ++j) {
            int n = n0 + j * 8 + ((lane & 3) << 1);
            float b0 = bias[n], b1 = bias[n + 1];
            float2 v0 = make_float2(acc[i][j][0] * inv + b0, acc[i][j][1] * inv + b1);
            float2 v1 = make_float2(acc[i][j][2] * inv + b0, acc[i][j][3] * inv + b1);
            *reinterpret_cast<float2*>(&out[(size_t)m * NDIM + n]) = v0;
            *reinterpret_cast<float2*>(&out[(size_t)(m + 8) * NDIM + n]) = v1;
        }
    }
}

// ---------------- 4 launches; GEMM is launch #4 (profiled slot) ----------------
extern "C" void kernel_launch(void* const* d_in, const int* in_sizes, int n_in,
                              void* d_out, int out_size) {
    const float* x    = (const float*)d_in[0];
    const float* w    = (const float*)d_in[1];
    const float* bias = (const float*)d_in[2];
    float* out = (float*)d_out;

    amax_fused_kernel<<<XAB + WAB, 256>>>((const float4*)x, (const float4*)w);
    scales_kernel<<<1, 1024>>>();
    quant_fused_kernel<<<2048 + 4096, 256>>>((const float4*)x, (const float4*)w);

    static bool attr_done = false;
    if (!attr_done) {
        cudaFuncSetAttribute(gemm_fp8_kernel,
                             cudaFuncAttributeMaxDynamicSharedMemorySize, SMEM_TOT);
        attr_done = true;
    }
    dim3 grid(MDIM / BM, NDIM / BN);   // (64, 128): M fastest; A panel L2-resident
    gemm_fp8_kernel<<<grid, 128, SMEM_TOT>>>(bias, out);
}

// round 13
// speedup vs baseline: 1.7095x; 1.1814x over previous
#include <cuda_runtime.h>
#include <cuda_bf16.h>
#include <cstdint>
#include <cstddef>

// Problem dims: x [4,2048,4096] -> M=8192, K=4096; w [16384,4096] -> N=16384
#define MDIM 8192
#define KDIM 4096
#define NDIM 16384
#define MAXV 448.0f
#define EPSV 1e-12f

#define XAB 1024
#define WAB 2048

// ---------------- device scratch ----------------
__device__ float g_part[XAB + WAB];
__device__ float g_scales[3];                       // sx, sw, 1/(sx*sw)
__device__ uint8_t g_xq[(size_t)MDIM * KDIM];       // 32 MB e4m3 (scaled domain)
__device__ uint8_t g_wq[(size_t)NDIM * KDIM];       // 64 MB e4m3 (scaled domain)

// ---------------- launch 1: fused amax partials (4 indep accumulators) ----------------
__global__ void amax_fused_kernel(const float4* __restrict__ x, const float4* __restrict__ w) {
    __shared__ float sred[16];
    int seg = (blockIdx.x < XAB) ? 0 : 1;
    const float4* p = seg ? w : x;
    size_t n4 = seg ? ((size_t)NDIM * KDIM / 4) : ((size_t)MDIM * KDIM / 4);
    int b = seg ? (blockIdx.x - XAB) : blockIdx.x;
    size_t nb = seg ? WAB : XAB;

    float m0 = 0.f, m1 = 0.f, m2 = 0.f, m3 = 0.f;
    size_t stride = nb * blockDim.x;
    for (size_t i = (size_t)b * blockDim.x + threadIdx.x; i < n4; i += stride) {
        float4 v = p[i];
        m0 = fmaxf(m0, fabsf(v.x));
        m1 = fmaxf(m1, fabsf(v.y));
        m2 = fmaxf(m2, fabsf(v.z));
        m3 = fmaxf(m3, fabsf(v.w));
    }
    float m = fminf(fmaxf(fmaxf(m0, m1), fmaxf(m2, m3)), MAXV);
#pragma unroll
    for (int o = 16; o > 0; o >>= 1) m = fmaxf(m, __shfl_xor_sync(0xffffffffu, m, o));
    if ((threadIdx.x & 31) == 0) sred[threadIdx.x >> 5] = m;
    __syncthreads();
    if (threadIdx.x == 0) {
        float r = sred[0];
        int nw = blockDim.x >> 5;
        for (int i = 1; i < nw; ++i) r = fmaxf(r, sred[i]);
        g_part[blockIdx.x] = r;
    }
}

// ---------------- launch 2: reduce partials -> scales ----------------
__global__ void scales_kernel() {
    __shared__ float sx_s[32], sw_s[32];
    int t = threadIdx.x, lane = t & 31, wrp = t >> 5;
    float mx = 0.f, mw = 0.f;
    for (int i = t; i < XAB; i += 1024) mx = fmaxf(mx, g_part[i]);
    for (int i = t; i < WAB; i += 1024) mw = fmaxf(mw, g_part[XAB + i]);
#pragma unroll
    for (int o = 16; o > 0; o >>= 1) {
        mx = fmaxf(mx, __shfl_xor_sync(0xffffffffu, mx, o));
        mw = fmaxf(mw, __shfl_xor_sync(0xffffffffu, mw, o));
    }
    if (lane == 0) { sx_s[wrp] = mx; sw_s[wrp] = mw; }
    __syncthreads();
    if (t == 0) {
        float ax = EPSV, aw = EPSV;
#pragma unroll
        for (int i = 0; i < 32; ++i) { ax = fmaxf(ax, sx_s[i]); aw = fmaxf(aw, sw_s[i]); }
        float sx = MAXV / ax, sw = MAXV / aw;
        g_scales[0] = sx;
        g_scales[1] = sw;
        g_scales[2] = (1.f / sx) * (1.f / sw);
    }
}

// ---------------- fake-quantize in scaled domain, pack to e4m3 ----------------
__device__ __forceinline__ float fqs(float v, float scale) {
    float c = fminf(fmaxf(v, -MAXV), MAXV);
    float s = c * scale;
    float mag = fmaxf(fabsf(s), EPSV);
    int e;
    frexpf(mag, &e);
    float r = rintf(ldexpf(mag, 4 - e));
    float q = ldexpf(r, e - 4);
    return copysignf(q, s);
}

__device__ __forceinline__ uint32_t pack4_e4m3(float a, float b, float c, float d) {
    uint16_t lo, hi;
    asm("cvt.rn.satfinite.e4m3x2.f32 %0, %2, %1;" : "=h"(lo) : "f"(a), "f"(b));
    asm("cvt.rn.satfinite.e4m3x2.f32 %0, %2, %1;" : "=h"(hi) : "f"(c), "f"(d));
    return (uint32_t)lo | ((uint32_t)hi << 16);
}

// ---------------- launch 3: fused quantize ----------------
#define QXB 1024
#define QWB 2048
__global__ void quant_fused_kernel(const float4* __restrict__ x, const float4* __restrict__ w) {
    int seg = (blockIdx.x < QXB) ? 0 : 1;
    const float4* in = seg ? w : x;
    uint32_t* outq = (uint32_t*)(seg ? g_wq : g_xq);
    size_t n4 = seg ? ((size_t)NDIM * KDIM / 4) : ((size_t)MDIM * KDIM / 4);
    int b = seg ? (blockIdx.x - QXB) : blockIdx.x;
    size_t nb = seg ? QWB : QXB;
    float s = g_scales[seg];
    size_t stride = nb * blockDim.x;
    for (size_t i = (size_t)b * blockDim.x + threadIdx.x; i < n4; i += stride) {
        float4 v = in[i];
        outq[i] = pack4_e4m3(fqs(v.x, s), fqs(v.y, s), fqs(v.z, s), fqs(v.w, s));
    }
}

// =======================================================================
// launch 4: FP8 mma.sync GEMM (R8 structure), CTA 128x128, warp tile
// 64x64, BK=64, 4-stage cp.async. ldsm(ks0) pre-barrier; wait_group 2.
// =======================================================================
#define BM 128
#define BN 128
#define BK 64
#define STAGES 4
#define NKIT (KDIM / BK)            // 64
#define PITCHB 80
#define TILE_B (128 * PITCHB)       // 10240
#define STAGE_B (2 * TILE_B)        // 20480
#define SMEM_TOT (STAGES * STAGE_B) // 81920

__device__ __forceinline__ uint32_t smem_u32(const void* p) {
    return (uint32_t)__cvta_generic_to_shared(p);
}
__device__ __forceinline__ void cp16s(uint32_t dst, const void* src) {
    asm volatile("cp.async.cg.shared.global [%0], [%1], 16;\n" :: "r"(dst), "l"(src));
}
__device__ __forceinline__ void ldsm_x4(uint32_t* r, uint32_t addr) {
    asm volatile("ldmatrix.sync.aligned.m8n8.x4.shared.b16 {%0,%1,%2,%3}, [%4];\n"
                 : "=r"(r[0]), "=r"(r[1]), "=r"(r[2]), "=r"(r[3]) : "r"(addr));
}
__device__ __forceinline__ void mma_fp8(float* c, const uint32_t* a, const uint32_t* b) {
    asm volatile("mma.sync.aligned.m16n8k32.row.col.f32.e4m3.e4m3.f32 "
                 "{%0,%1,%2,%3}, {%4,%5,%6,%7}, {%8,%9}, {%0,%1,%2,%3};\n"
                 : "+f"(c[0]), "+f"(c[1]), "+f"(c[2]), "+f"(c[3])
                 : "r"(a[0]), "r"(a[1]), "r"(a[2]), "r"(a[3]), "r"(b[0]), "r"(b[1]));
}

__device__ __forceinline__ void load_stage(uint8_t* smem, int s,
                                           const uint8_t* __restrict__ gA,
                                           const uint8_t* __restrict__ gB,
                                           int k0, int tid) {
    uint32_t stA = smem_u32(smem + (size_t)s * STAGE_B);
    uint32_t stB = stA + TILE_B;
#pragma unroll
    for (int j = 0; j < 8; ++j) {
        int chunk = j * 128 + tid;
        if (j < 4) {
            int r = chunk >> 2, c = (chunk & 3) * 16;
            cp16s(stA + r * PITCHB + c, gA + (size_t)r * KDIM + k0 + c);
        } else {
            int bc = chunk - 512;
            int r = bc >> 2, c = (bc & 3) * 16;
            cp16s(stB + r * PITCHB + c, gB + (size_t)r * KDIM + k0 + c);
        }
    }
    asm volatile("cp.async.commit_group;\n" ::: "memory");
}

// per-warp fragment load for one k32 step (ks = 0 or 1)
__device__ __forceinline__ void load_frags(uint32_t stA, uint32_t stB, int wm, int wn,
                                           int lane, int ks,
                                           uint32_t a[4][4], uint32_t b[8][2]) {
#pragma unroll
    for (int i = 0; i < 4; ++i) {
        uint32_t addr = stA + (wm + i * 16 + (lane & 15)) * PITCHB
                            + ks * 32 + (lane >> 4) * 16;
        ldsm_x4(a[i], addr);
    }
#pragma unroll
    for (int jj = 0; jj < 4; ++jj) {
        int g = lane >> 3;
        int row = wn + jj * 16 + ((g >> 1) << 3) + (lane & 7);
        int col = ks * 32 + ((g & 1) << 4);
        uint32_t r[4];
        ldsm_x4(r, stB + row * PITCHB + col);
        b[2 * jj][0] = r[0]; b[2 * jj][1] = r[1];
        b[2 * jj + 1][0] = r[2]; b[2 * jj + 1][1] = r[3];
    }
}

__global__ void __launch_bounds__(128, 2)
gemm_fp8_kernel(const float* __restrict__ bias, float* __restrict__ out) {
    extern __shared__ uint8_t smem[];

    int tid = threadIdx.x;
    int lane = tid & 31, warp = tid >> 5;
    int wm = (warp >> 1) * 64;
    int wn = (warp & 1) * 64;
    int mblk = blockIdx.x, nblk = blockIdx.y;

    const uint8_t* gA = g_xq + (size_t)mblk * BM * KDIM;
    const uint8_t* gB = g_wq + (size_t)nblk * BN * KDIM;

    float acc[4][8][4];
#pragma unroll
    for (int i = 0; i < 4; ++i)
#pragma unroll
        for (int j = 0; j < 8; ++j)
#pragma unroll
            for (int k = 0; k < 4; ++k) acc[i][j][k] = 0.f;

    load_stage(smem, 0, gA, gB, 0, tid);
    load_stage(smem, 1, gA, gB, BK, tid);
    load_stage(smem, 2, gA, gB, 2 * BK, tid);

    // make stage 0 complete + visible for the hoisted ldsm of iter 0
    asm volatile("cp.async.wait_group 2;\n" ::: "memory");
    __syncthreads();

    for (int kt = 0; kt < NKIT; ++kt) {
        uint32_t stA = smem_u32(smem + (size_t)(kt & (STAGES - 1)) * STAGE_B);
        uint32_t stB = stA + TILE_B;

        // ks0 fragments before the barrier: stage kt complete (wait_group at
        // iter kt-1 left <=2 pending: stages kt+1,kt+2) and visible (previous
        // barrier). Latency hides under barrier wait.
        uint32_t a[4][4], b[8][2];
        load_frags(stA, stB, wm, wn, lane, 0, a, b);

        // need stage kt+1 complete before this barrier (next iter's pre-barrier
        // ldsm). 3 groups in flight -> wait_group 2 leaves only kt+2,kt+3 pending.
        asm volatile("cp.async.wait_group 2;\n" ::: "memory");
        __syncthreads();

        if (kt + 3 < NKIT)
            load_stage(smem, (kt + 3) & (STAGES - 1), gA, gB, (kt + 3) * BK, tid);

#pragma unroll
        for (int i = 0; i < 4; ++i)
#pragma unroll
            for (int j = 0; j < 8; ++j)
                mma_fp8(acc[i][j], a[i], b[j]);

        // ks1 fragments (reuse regs), then second MMA batch
        load_frags(stA, stB, wm, wn, lane, 1, a, b);
#pragma unroll
        for (int i = 0; i < 4; ++i)
#pragma unroll
            for (int j = 0; j < 8; ++j)
                mma_fp8(acc[i][j], a[i], b[j]);
    }

    float inv = g_scales[2];
    int m0 = mblk * BM + wm;
    int n0 = nblk * BN + wn;
#pragma unroll
    for (int i = 0; i < 4; ++i) {
        int m = m0 + i * 16 + (lane >> 2);
#pragma unroll
        for (int j = 0; j < 8; ++j) {
            int n = n0 + j * 8 + ((lane & 3) << 1);
            float b0 = __ldg(&bias[n]), b1 = __ldg(&bias[n + 1]);
            float2 v0 = make_float2(acc[i][j][0] * inv + b0, acc[i][j][1] * inv + b1);
            float2 v1 = make_float2(acc[i][j][2] * inv + b0, acc[i][j][3] * inv + b1);
            *reinterpret_cast<float2*>(&out[(size_t)m * NDIM + n]) = v0;
            *reinterpret_cast<float2*>(&out[(size_t)(m + 8) * NDIM + n]) = v1;
        }
    }
}

// ---------------- 4 launches; GEMM is launch #4 (profiled slot) ----------------
extern "C" void kernel_launch(void* const* d_in, const int* in_sizes, int n_in,
                              void* d_out, int out_size) {
    const float* x    = (const float*)d_in[0];
    const float* w    = (const float*)d_in[1];
    const float* bias = (const float*)d_in[2];
    float* out = (float*)d_out;

    amax_fused_kernel<<<XAB + WAB, 512>>>((const float4*)x, (const float4*)w);
    scales_kernel<<<1, 1024>>>();
    quant_fused_kernel<<<QXB + QWB, 512>>>((const float4*)x, (const float4*)w);

    static bool attr_done = false;
    if (!attr_done) {
        cudaFuncSetAttribute(gemm_fp8_kernel,
                             cudaFuncAttributeMaxDynamicSharedMemorySize, SMEM_TOT);
        attr_done = true;
    }
    dim3 grid(MDIM / BM, NDIM / BN);   // (64, 128): M fastest; A panel L2-resident
    gemm_fp8_kernel<<<grid, 128, SMEM_TOT>>>(bias, out);
}

// round 14
// speedup vs baseline: 1.7642x; 1.0320x over previous
#include <cuda_runtime.h>
#include <cuda_bf16.h>
#include <cstdint>
#include <cstddef>

// Problem dims: x [4,2048,4096] -> M=8192, K=4096; w [16384,4096] -> N=16384
#define MDIM 8192
#define KDIM 4096
#define NDIM 16384
#define MAXV 448.0f
#define EPSV 1e-12f

#define XAB 1024
#define WAB 2048

// ---------------- device scratch ----------------
__device__ float g_part[XAB + WAB];
__device__ float g_scales[3];                       // sx, sw, 1/(sx*sw)
__device__ uint8_t g_xq[(size_t)MDIM * KDIM];       // 32 MB e4m3 (scaled domain)
__device__ uint8_t g_wq[(size_t)NDIM * KDIM];       // 64 MB e4m3 (scaled domain)

// ---------------- launch 1: fused amax partials (4 indep accumulators) ----------------
__global__ void amax_fused_kernel(const float4* __restrict__ x, const float4* __restrict__ w) {
    __shared__ float sred[16];
    int seg = (blockIdx.x < XAB) ? 0 : 1;
    const float4* p = seg ? w : x;
    size_t n4 = seg ? ((size_t)NDIM * KDIM / 4) : ((size_t)MDIM * KDIM / 4);
    int b = seg ? (blockIdx.x - XAB) : blockIdx.x;
    size_t nb = seg ? WAB : XAB;

    float m0 = 0.f, m1 = 0.f, m2 = 0.f, m3 = 0.f;
    size_t stride = nb * blockDim.x;
    for (size_t i = (size_t)b * blockDim.x + threadIdx.x; i < n4; i += stride) {
        float4 v = p[i];
        m0 = fmaxf(m0, fabsf(v.x));
        m1 = fmaxf(m1, fabsf(v.y));
        m2 = fmaxf(m2, fabsf(v.z));
        m3 = fmaxf(m3, fabsf(v.w));
    }
    float m = fminf(fmaxf(fmaxf(m0, m1), fmaxf(m2, m3)), MAXV);
#pragma unroll
    for (int o = 16; o > 0; o >>= 1) m = fmaxf(m, __shfl_xor_sync(0xffffffffu, m, o));
    if ((threadIdx.x & 31) == 0) sred[threadIdx.x >> 5] = m;
    __syncthreads();
    if (threadIdx.x == 0) {
        float r = sred[0];
        int nw = blockDim.x >> 5;
        for (int i = 1; i < nw; ++i) r = fmaxf(r, sred[i]);
        g_part[blockIdx.x] = r;
    }
}

// ---------------- launch 2: reduce partials -> scales ----------------
__global__ void scales_kernel() {
    __shared__ float sx_s[32], sw_s[32];
    int t = threadIdx.x, lane = t & 31, wrp = t >> 5;
    float mx = 0.f, mw = 0.f;
    for (int i = t; i < XAB; i += 1024) mx = fmaxf(mx, g_part[i]);
    for (int i = t; i < WAB; i += 1024) mw = fmaxf(mw, g_part[XAB + i]);
#pragma unroll
    for (int o = 16; o > 0; o >>= 1) {
        mx = fmaxf(mx, __shfl_xor_sync(0xffffffffu, mx, o));
        mw = fmaxf(mw, __shfl_xor_sync(0xffffffffu, mw, o));
    }
    if (lane == 0) { sx_s[wrp] = mx; sw_s[wrp] = mw; }
    __syncthreads();
    if (t == 0) {
        float ax = EPSV, aw = EPSV;
#pragma unroll
        for (int i = 0; i < 32; ++i) { ax = fmaxf(ax, sx_s[i]); aw = fmaxf(aw, sw_s[i]); }
        float sx = MAXV / ax, sw = MAXV / aw;
        g_scales[0] = sx;
        g_scales[1] = sw;
        g_scales[2] = (1.f / sx) * (1.f / sw);
    }
}

// ---------------- direct e4m3 quantize: clamp -> scale -> cvt.rn.satfinite ----------------
// For |scaled| >= 2^-6 the reference's power-of-two-step rounding IS e4m3
// round-half-even, so the double rounding (fqs then cvt) collapses to one cvt.
__device__ __forceinline__ uint32_t quant4(float4 v, float s) {
    float a = fminf(fmaxf(v.x, -MAXV), MAXV) * s;
    float b = fminf(fmaxf(v.y, -MAXV), MAXV) * s;
    float c = fminf(fmaxf(v.z, -MAXV), MAXV) * s;
    float d = fminf(fmaxf(v.w, -MAXV), MAXV) * s;
    uint16_t lo, hi;
    asm("cvt.rn.satfinite.e4m3x2.f32 %0, %2, %1;" : "=h"(lo) : "f"(a), "f"(b));
    asm("cvt.rn.satfinite.e4m3x2.f32 %0, %2, %1;" : "=h"(hi) : "f"(c), "f"(d));
    return (uint32_t)lo | ((uint32_t)hi << 16);
}

// ---------------- launch 3: fused quantize (memory-bound now) ----------------
#define QXB 1024
#define QWB 2048
__global__ void quant_fused_kernel(const float4* __restrict__ x, const float4* __restrict__ w) {
    int seg = (blockIdx.x < QXB) ? 0 : 1;
    const float4* in = seg ? w : x;
    uint32_t* outq = (uint32_t*)(seg ? g_wq : g_xq);
    size_t n4 = seg ? ((size_t)NDIM * KDIM / 4) : ((size_t)MDIM * KDIM / 4);
    int b = seg ? (blockIdx.x - QXB) : blockIdx.x;
    size_t nb = seg ? QWB : QXB;
    float s = g_scales[seg];
    size_t stride = nb * blockDim.x;
    size_t i = (size_t)b * blockDim.x + threadIdx.x;
    // 2-way unrolled independent chains (n4 is a multiple of 2*stride-safe bounds)
    for (; i + stride < n4; i += 2 * stride) {
        float4 v0 = in[i];
        float4 v1 = in[i + stride];
        uint32_t q0 = quant4(v0, s);
        uint32_t q1 = quant4(v1, s);
        outq[i] = q0;
        outq[i + stride] = q1;
    }
    if (i < n4) outq[i] = quant4(in[i], s);
}

// =======================================================================
// launch 4: FP8 mma.sync GEMM (R8/R13 structure, UNCHANGED - local optimum)
// =======================================================================
#define BM 128
#define BN 128
#define BK 64
#define STAGES 4
#define NKIT (KDIM / BK)            // 64
#define PITCHB 80
#define TILE_B (128 * PITCHB)       // 10240
#define STAGE_B (2 * TILE_B)        // 20480
#define SMEM_TOT (STAGES * STAGE_B) // 81920

__device__ __forceinline__ uint32_t smem_u32(const void* p) {
    return (uint32_t)__cvta_generic_to_shared(p);
}
__device__ __forceinline__ void cp16s(uint32_t dst, const void* src) {
    asm volatile("cp.async.cg.shared.global [%0], [%1], 16;\n" :: "r"(dst), "l"(src));
}
__device__ __forceinline__ void ldsm_x4(uint32_t* r, uint32_t addr) {
    asm volatile("ldmatrix.sync.aligned.m8n8.x4.shared.b16 {%0,%1,%2,%3}, [%4];\n"
                 : "=r"(r[0]), "=r"(r[1]), "=r"(r[2]), "=r"(r[3]) : "r"(addr));
}
__device__ __forceinline__ void mma_fp8(float* c, const uint32_t* a, const uint32_t* b) {
    asm volatile("mma.sync.aligned.m16n8k32.row.col.f32.e4m3.e4m3.f32 "
                 "{%0,%1,%2,%3}, {%4,%5,%6,%7}, {%8,%9}, {%0,%1,%2,%3};\n"
                 : "+f"(c[0]), "+f"(c[1]), "+f"(c[2]), "+f"(c[3])
                 : "r"(a[0]), "r"(a[1]), "r"(a[2]), "r"(a[3]), "r"(b[0]), "r"(b[1]));
}

__device__ __forceinline__ void load_stage(uint8_t* smem, int s,
                                           const uint8_t* __restrict__ gA,
                                           const uint8_t* __restrict__ gB,
                                           int k0, int tid) {
    uint32_t stA = smem_u32(smem + (size_t)s * STAGE_B);
    uint32_t stB = stA + TILE_B;
#pragma unroll
    for (int j = 0; j < 8; ++j) {
        int chunk = j * 128 + tid;
        if (j < 4) {
            int r = chunk >> 2, c = (chunk & 3) * 16;
            cp16s(stA + r * PITCHB + c, gA + (size_t)r * KDIM + k0 + c);
        } else {
            int bc = chunk - 512;
            int r = bc >> 2, c = (bc & 3) * 16;
            cp16s(stB + r * PITCHB + c, gB + (size_t)r * KDIM + k0 + c);
        }
    }
    asm volatile("cp.async.commit_group;\n" ::: "memory");
}

__device__ __forceinline__ void load_frags(uint32_t stA, uint32_t stB, int wm, int wn,
                                           int lane, int ks,
                                           uint32_t a[4][4], uint32_t b[8][2]) {
#pragma unroll
    for (int i = 0; i < 4; ++i) {
        uint32_t addr = stA + (wm + i * 16 + (lane & 15)) * PITCHB
                            + ks * 32 + (lane >> 4) * 16;
        ldsm_x4(a[i], addr);
    }
#pragma unroll
    for (int jj = 0; jj < 4; ++jj) {
        int g = lane >> 3;
        int row = wn + jj * 16 + ((g >> 1) << 3) + (lane & 7);
        int col = ks * 32 + ((g & 1) << 4);
        uint32_t r[4];
        ldsm_x4(r, stB + row * PITCHB + col);
        b[2 * jj][0] = r[0]; b[2 * jj][1] = r[1];
        b[2 * jj + 1][0] = r[2]; b[2 * jj + 1][1] = r[3];
    }
}

__global__ void __launch_bounds__(128, 2)
gemm_fp8_kernel(const float* __restrict__ bias, float* __restrict__ out) {
    extern __shared__ uint8_t smem[];

    int tid = threadIdx.x;
    int lane = tid & 31, warp = tid >> 5;
    int wm = (warp >> 1) * 64;
    int wn = (warp & 1) * 64;
    int mblk = blockIdx.x, nblk = blockIdx.y;

    const uint8_t* gA = g_xq + (size_t)mblk * BM * KDIM;
    const uint8_t* gB = g_wq + (size_t)nblk * BN * KDIM;

    float acc[4][8][4];
#pragma unroll
    for (int i = 0; i < 4; ++i)
#pragma unroll
        for (int j = 0; j < 8; ++j)
#pragma unroll
            for (int k = 0; k < 4; ++k) acc[i][j][k] = 0.f;

    load_stage(smem, 0, gA, gB, 0, tid);
    load_stage(smem, 1, gA, gB, BK, tid);
    load_stage(smem, 2, gA, gB, 2 * BK, tid);

    asm volatile("cp.async.wait_group 2;\n" ::: "memory");
    __syncthreads();

    for (int kt = 0; kt < NKIT; ++kt) {
        uint32_t stA = smem_u32(smem + (size_t)(kt & (STAGES - 1)) * STAGE_B);
        uint32_t stB = stA + TILE_B;

        uint32_t a[4][4], b[8][2];
        load_frags(stA, stB, wm, wn, lane, 0, a, b);

        asm volatile("cp.async.wait_group 2;\n" ::: "memory");
        __syncthreads();

        if (kt + 3 < NKIT)
            load_stage(smem, (kt + 3) & (STAGES - 1), gA, gB, (kt + 3) * BK, tid);

#pragma unroll
        for (int i = 0; i < 4; ++i)
#pragma unroll
            for (int j = 0; j < 8; ++j)
                mma_fp8(acc[i][j], a[i], b[j]);

        load_frags(stA, stB, wm, wn, lane, 1, a, b);
#pragma unroll
        for (int i = 0; i < 4; ++i)
#pragma unroll
            for (int j = 0; j < 8; ++j)
                mma_fp8(acc[i][j], a[i], b[j]);
    }

    float inv = g_scales[2];
    int m0 = mblk * BM + wm;
    int n0 = nblk * BN + wn;
#pragma unroll
    for (int i = 0; i < 4; ++i) {
        int m = m0 + i * 16 + (lane >> 2);
#pragma unroll
        for (int j = 0; j < 8; ++j) {
            int n = n0 + j * 8 + ((lane & 3) << 1);
            float b0 = __ldg(&bias[n]), b1 = __ldg(&bias[n + 1]);
            float2 v0 = make_float2(acc[i][j][0] * inv + b0, acc[i][j][1] * inv + b1);
            float2 v1 = make_float2(acc[i][j][2] * inv + b0, acc[i][j][3] * inv + b1);
            *reinterpret_cast<float2*>(&out[(size_t)m * NDIM + n]) = v0;
            *reinterpret_cast<float2*>(&out[(size_t)(m + 8) * NDIM + n]) = v1;
        }
    }
}

// ---------------- 4 launches; GEMM is launch #4 (profiled slot) ----------------
extern "C" void kernel_launch(void* const* d_in, const int* in_sizes, int n_in,
                              void* d_out, int out_size) {
    const float* x    = (const float*)d_in[0];
    const float* w    = (const float*)d_in[1];
    const float* bias = (const float*)d_in[2];
    float* out = (float*)d_out;

    amax_fused_kernel<<<XAB + WAB, 512>>>((const float4*)x, (const float4*)w);
    scales_kernel<<<1, 1024>>>();
    quant_fused_kernel<<<QXB + QWB, 512>>>((const float4*)x, (const float4*)w);

    static bool attr_done = false;
    if (!attr_done) {
        cudaFuncSetAttribute(gemm_fp8_kernel,
                             cudaFuncAttributeMaxDynamicSharedMemorySize, SMEM_TOT);
        attr_done = true;
    }
    dim3 grid(MDIM / BM, NDIM / BN);   // (64, 128): M fastest; A panel L2-resident
    gemm_fp8_kernel<<<grid, 128, SMEM_TOT>>>(bias, out);
}